// round 16
// baseline (speedup 1.0000x reference)
#include <cuda_runtime.h>
#include <cstdint>

#define DD    2048
#define NBLK  16
#define BATCH 32

// Scratch (no allocations allowed -> __device__ globals; protocol-reset)
__device__ float g_part[BATCH * 4 * NBLK];   // gate logit partials
__device__ int   g_arrive = 0;               // gate arrival counter
__device__ int   g_done   = 0;               // grid completion counter
__device__ volatile int g_ready = 0;         // gates-finalized flag
__device__ int   g_cnt[NBLK];
__device__ int   g_idx[NBLK * 32];
__device__ float g_gval[NBLK * 32];

__device__ __forceinline__ unsigned long long ffma2(
    unsigned long long a, unsigned long long b, unsigned long long c)
{
    unsigned long long d;
    asm("fma.rn.f32x2 %0, %1, %2, %3;" : "=l"(d) : "l"(a), "l"(b), "l"(c));
    return d;
}

// ---------------------------------------------------------------------------
// ONE fused kernel. grid=512, block=512, 2 CTAs/SM (<=64 regs, 33 KB smem).
//  bids 0..127 : gate partials (b=bid>>2, slice=bid&3) + bias fill; last
//                arrival finalizes gates+compaction, raises g_ready.
//  all bids    : spin g_ready, then gated GEMM tile=bid&63, chunk=bid>>6
//                (4 compacted slots per chunk). Idle chunks exit fast.
// ---------------------------------------------------------------------------
__global__ __launch_bounds__(512, 2) void fused_kernel(
    const float* __restrict__ x, const float* __restrict__ gw,
    const float* __restrict__ gb, const float* __restrict__ W,
    const float* __restrict__ bias, float* __restrict__ out)
{
    extern __shared__ float smem[];
    float* xs  = smem;              // 4 rows x 2048 floats (32 KB)
    float* red = smem;              // aliased after loop: 128 x 65 floats

    const int bid = blockIdx.x;
    const int tid = threadIdx.x;

    // ================= gate phase (bids 0..127) =================
    if (bid < 128) {
        const int b  = bid >> 2;
        const int sl = bid & 3;
        const int k  = sl * 512 + tid;

        __shared__ float ws[16][NBLK + 1];
        __shared__ int   lastflag;
        if (tid == 0) lastflag = 0;

        // bias fill for this (b, slice) range: 512 floats = 128 float4
        if (tid < 128)
            ((float4*)(out + (size_t)b * DD + sl * 512))[tid] =
                ((const float4*)(bias + sl * 512))[tid];

        float p[NBLK];
        {
            const float xv = x[(size_t)b * DD + k];
            const float4* gr = (const float4*)(gw + (size_t)k * NBLK);
            const float4 w0 = gr[0], w1 = gr[1], w2 = gr[2], w3 = gr[3];
            p[0]=xv*w0.x;  p[1]=xv*w0.y;  p[2]=xv*w0.z;  p[3]=xv*w0.w;
            p[4]=xv*w1.x;  p[5]=xv*w1.y;  p[6]=xv*w1.z;  p[7]=xv*w1.w;
            p[8]=xv*w2.x;  p[9]=xv*w2.y;  p[10]=xv*w2.z; p[11]=xv*w2.w;
            p[12]=xv*w3.x; p[13]=xv*w3.y; p[14]=xv*w3.z; p[15]=xv*w3.w;
        }
#pragma unroll
        for (int j = 0; j < NBLK; j++)
#pragma unroll
            for (int off = 16; off > 0; off >>= 1)
                p[j] += __shfl_xor_sync(0xffffffffu, p[j], off);

        if ((tid & 31) == 0) {
#pragma unroll
            for (int j = 0; j < NBLK; j++) ws[tid >> 5][j] = p[j];
        }
        __syncthreads();
        if (tid < NBLK) {
            float s = 0.f;
#pragma unroll
            for (int w = 0; w < 16; w++) s += ws[w][tid];
            g_part[((size_t)b * 4 + sl) * NBLK + tid] = s;
        }
        __syncthreads();
        if (tid == 0) {
            __threadfence();
            if (atomicAdd(&g_arrive, 1) == 127) lastflag = 1;
        }
        __syncthreads();

        if (lastflag) {                      // ---- finalize gates ----
            __threadfence();
            __shared__ float sgate[BATCH][NBLK + 1];
            if (tid < BATCH) {
                float v[NBLK];
                const float4* gb4 = (const float4*)gb;
                {
                    const float4 b0 = gb4[0], b1 = gb4[1], b2 = gb4[2], b3 = gb4[3];
                    v[0]=b0.x;  v[1]=b0.y;  v[2]=b0.z;  v[3]=b0.w;
                    v[4]=b1.x;  v[5]=b1.y;  v[6]=b1.z;  v[7]=b1.w;
                    v[8]=b2.x;  v[9]=b2.y;  v[10]=b2.z; v[11]=b2.w;
                    v[12]=b3.x; v[13]=b3.y; v[14]=b3.z; v[15]=b3.w;
                }
#pragma unroll
                for (int s = 0; s < 4; s++) {
                    const float4* pp =
                        (const float4*)(g_part + ((size_t)tid * 4 + s) * NBLK);
                    const float4 p0 = pp[0], p1 = pp[1], p2 = pp[2], p3 = pp[3];
                    v[0]+=p0.x;  v[1]+=p0.y;  v[2]+=p0.z;  v[3]+=p0.w;
                    v[4]+=p1.x;  v[5]+=p1.y;  v[6]+=p1.z;  v[7]+=p1.w;
                    v[8]+=p2.x;  v[9]+=p2.y;  v[10]+=p2.z; v[11]+=p2.w;
                    v[12]+=p3.x; v[13]+=p3.y; v[14]+=p3.z; v[15]+=p3.w;
                }
#pragma unroll
                for (int j = 0; j < NBLK; j++) v[j] = 1.f / (1.f + expf(-v[j]));

                unsigned mask = 0;   // drop 8 smallest; '<' => lowest idx on ties
                for (int it = 0; it < NBLK / 2; it++) {
                    int best = 0; float bv = 3.4e38f;
                    for (int j = 0; j < NBLK; j++)
                        if (!((mask >> j) & 1u) && v[j] < bv) { bv = v[j]; best = j; }
                    mask |= 1u << best;
                }
#pragma unroll
                for (int j = 0; j < NBLK; j++)
                    sgate[tid][j] = ((mask >> j) & 1u) ? 0.f : v[j];
            }
            __syncthreads();
            if (tid < 32) {                  // warp 0: compaction
                const int lane = tid;
                if (lane < NBLK) {
                    int cnt = 0;
                    for (int bb = 0; bb < BATCH; bb++) {
                        const float v = sgate[bb][lane];
                        if (v != 0.f) {
                            g_idx[lane * 32 + cnt] = bb;
                            g_gval[lane * 32 + cnt] = v; cnt++;
                        }
                    }
                    g_cnt[lane] = cnt;
                    for (int s = cnt; s < 32; s++) {
                        g_idx[lane * 32 + s] = 0; g_gval[lane * 32 + s] = 0.f;
                    }
                }
                if (lane == 0) { g_arrive = 0; __threadfence(); g_ready = 1; }
            }
        }
    }

    // ================= wait for gates (finalizer is wave-1 resident) ========
    if (tid == 0) {
        while (g_ready == 0) __nanosleep(40);
    }
    __syncthreads();
    __threadfence();

    const int tile = bid & 63;
    const int chnk = bid >> 6;           // 0..7
    const int nb   = tile >> 2;
    const int c0   = tile * 32;
    const int s0   = chnk * 4;

    __shared__ int   s_bidx[4];
    __shared__ float s_gvl[4];
    __shared__ int   s_cnt;
    if (tid < 4) {
        s_bidx[tid] = g_idx[nb * 32 + s0 + tid];   // padded slots: b=0
        s_gvl[tid]  = g_gval[nb * 32 + s0 + tid];
        if (tid == 0) s_cnt = g_cnt[nb];
    }
    __syncthreads();
    const int cnt = s_cnt;

    if (s0 >= cnt) {                     // idle chunk: outputs stay = bias
        if (tid == 0) {
            __threadfence();
            if (atomicAdd(&g_done, 1) == (int)gridDim.x - 1) {
                g_done = 0; g_ready = 0;
            }
        }
        return;
    }

    // stage x rows (coalesced float4): 4 rows x 512 float4
    for (int m = tid; m < 2048; m += 512) {
        const int s  = m >> 9;
        const int k4 = m & 511;
        ((float4*)(xs + s * DD))[k4] =
            ((const float4*)(x + (size_t)s_bidx[s] * DD))[k4];
    }
    __syncthreads();

    const int kg = tid & 63;             // 0..63 k-quad groups (lanes contiguous)
    const int cg = tid >> 6;             // 0..7 col-groups x 4 rows = 32 rows

    // W rows for this thread's 4 output columns, as k-quad (16 B) stream
    const ulonglong2* w128 = (const ulonglong2*)(W + (size_t)(c0 + cg * 4) * DD);

    unsigned long long acc[4][4];
#pragma unroll
    for (int s = 0; s < 4; s++)
#pragma unroll
        for (int c = 0; c < 4; c++) acc[s][c] = 0ull;

#pragma unroll
    for (int i = 0; i < 8; i++) {        // 8 superiters x 4 k-values
        const int q = kg + i * 64;       // k-quad index (k = 4q..4q+3)

        ulonglong2 wv[4];                // 4x LDG.128
#pragma unroll
        for (int c = 0; c < 4; c++) wv[c] = w128[c * 512 + q];

        ulonglong2 xv[4];                // 4x LDS.128
#pragma unroll
        for (int s = 0; s < 4; s++)
            xv[s] = *(const ulonglong2*)(xs + s * DD + (q << 2));

#pragma unroll
        for (int c = 0; c < 4; c++) {
#pragma unroll
            for (int s = 0; s < 4; s++) {
                acc[s][c] = ffma2(xv[s].x, wv[c].x, acc[s][c]);
                acc[s][c] = ffma2(xv[s].y, wv[c].y, acc[s][c]);
            }
        }
    }
    __syncthreads();                     // xs dead; alias as reduction buffer

    // horizontal add, conflict-free partial store:
    // red[(s*32 + cg*4 + c)*65 + kg] -> bank (idx + kg) % 32, all distinct
#pragma unroll
    for (int s = 0; s < 4; s++) {
#pragma unroll
        for (int c = 0; c < 4; c++) {
            const unsigned long long v = acc[s][c];
            const float lo = __uint_as_float((unsigned)(v & 0xffffffffu));
            const float hi = __uint_as_float((unsigned)(v >> 32));
            red[(s * 32 + cg * 4 + c) * 65 + kg] = lo + hi;
        }
    }
    __syncthreads();

    if (tid < 128) {
        const int s  = tid >> 5;         // local slot 0..3
        const int cp = tid & 31;         // local col 0..31
        const float* r = red + tid * 65;
        float a0 = 0.f, a1 = 0.f, a2 = 0.f, a3 = 0.f;
#pragma unroll
        for (int k = 0; k < 64; k += 4) {
            a0 += r[k]; a1 += r[k + 1]; a2 += r[k + 2]; a3 += r[k + 3];
        }
        const float sum = (a0 + a1) + (a2 + a3);
        if (s0 + s < cnt)
            out[(size_t)s_bidx[s] * DD + c0 + cp] = s_gvl[s] * sum + bias[c0 + cp];
    }
    __syncthreads();

    if (tid == 0) {                      // completion + flag reset
        __threadfence();
        if (atomicAdd(&g_done, 1) == (int)gridDim.x - 1) {
            g_done = 0; g_ready = 0;
        }
    }
}

// ---------------------------------------------------------------------------
extern "C" void kernel_launch(void* const* d_in, const int* in_sizes, int n_in,
                              void* d_out, int out_size)
{
    (void)in_sizes; (void)n_in; (void)out_size;
    const float* x    = (const float*)d_in[0];
    const float* gw   = (const float*)d_in[1];
    const float* gb   = (const float*)d_in[2];
    const float* W    = (const float*)d_in[3];
    const float* bias = (const float*)d_in[4];
    float* out = (float*)d_out;

    static int smem_set = 0;
    if (!smem_set) {
        cudaFuncSetAttribute(fused_kernel,
                             cudaFuncAttributeMaxDynamicSharedMemorySize,
                             128 * 65 * 4);   // 33280 B (xs 32 KB aliased inside)
        smem_set = 1;
    }

    fused_kernel<<<512, 512, 128 * 65 * 4>>>(x, gw, gb, W, bias, out);
}

// round 17
// speedup vs baseline: 1.2053x; 1.2053x over previous
#include <cuda_runtime.h>
#include <cstdint>

#define DD    2048
#define NBLK  16
#define BATCH 32

// Scratch (no allocations allowed): final gates (0 = dropped), fully
// rewritten by gate_kernel every launch.
__device__ float g_gates[BATCH * NBLK];

// ---------------------------------------------------------------------------
// Kernel 1 (proven R9): full gate network per batch. One CTA (512 thr) per
// batch. Computes logits, sigmoid, drops 8 smallest, writes final gates.
// Also fills out with bias (inactive (b,i) outputs are exactly bias[i]).
// ---------------------------------------------------------------------------
__global__ __launch_bounds__(512) void gate_kernel(
    const float* __restrict__ x, const float* __restrict__ gw,
    const float* __restrict__ gb, const float* __restrict__ bias,
    float* __restrict__ out)
{
    const int b   = blockIdx.x;
    const int tid = threadIdx.x;

    // bias fill for this batch row (coalesced float4)
    ((float4*)(out + (size_t)b * DD))[tid] = ((const float4*)bias)[tid];

    float p[NBLK];
#pragma unroll
    for (int j = 0; j < NBLK; j++) p[j] = 0.f;

#pragma unroll
    for (int r = 0; r < 4; r++) {
        const int k = r * 512 + tid;
        const float xv = x[(size_t)b * DD + k];
        const float4* gr = (const float4*)(gw + (size_t)k * NBLK);
        const float4 w0 = gr[0], w1 = gr[1], w2 = gr[2], w3 = gr[3];
        p[0]  += xv * w0.x;  p[1]  += xv * w0.y;  p[2]  += xv * w0.z;  p[3]  += xv * w0.w;
        p[4]  += xv * w1.x;  p[5]  += xv * w1.y;  p[6]  += xv * w1.z;  p[7]  += xv * w1.w;
        p[8]  += xv * w2.x;  p[9]  += xv * w2.y;  p[10] += xv * w2.z;  p[11] += xv * w2.w;
        p[12] += xv * w3.x;  p[13] += xv * w3.y;  p[14] += xv * w3.z;  p[15] += xv * w3.w;
    }

    // warp butterfly reduce (fixed order -> deterministic)
#pragma unroll
    for (int j = 0; j < NBLK; j++)
#pragma unroll
        for (int off = 16; off > 0; off >>= 1)
            p[j] += __shfl_xor_sync(0xffffffffu, p[j], off);

    __shared__ float ws[16][NBLK + 1];
    if ((tid & 31) == 0) {
#pragma unroll
        for (int j = 0; j < NBLK; j++) ws[tid >> 5][j] = p[j];
    }
    __syncthreads();

    __shared__ float gv[NBLK];
    if (tid < NBLK) {
        float s = 0.f;
#pragma unroll
        for (int w = 0; w < 16; w++) s += ws[w][tid];
        gv[tid] = 1.f / (1.f + expf(-(s + gb[tid])));
    }
    __syncthreads();

    if (tid == 0) {
        float v[NBLK];
#pragma unroll
        for (int j = 0; j < NBLK; j++) v[j] = gv[j];
        unsigned mask = 0;
        // drop the 8 smallest; strict '<' => lowest index wins ties (matches top_k)
        for (int it = 0; it < NBLK / 2; it++) {
            int best = 0; float bv = 3.4e38f;
            for (int j = 0; j < NBLK; j++)
                if (!((mask >> j) & 1u) && v[j] < bv) { bv = v[j]; best = j; }
            mask |= 1u << best;
        }
#pragma unroll
        for (int j = 0; j < NBLK; j++)
            g_gates[b * NBLK + j] = ((mask >> j) & 1u) ? 0.f : v[j];
    }
}

// ---------------------------------------------------------------------------
// Kernel 2: gated skinny GEMM. Dense self-computed worklist + 2 CTAs/SM.
// grid=304 (= 4 * max_items). CTA id -> item (id>>2) x col-tile (id&3).
// Each CTA's warp 0 rebuilds the item map from g_gates (ballots + prefix),
// so ACTIVE WORK OCCUPIES CONTIGUOUS LOW IDS and the tail exits instantly.
// ---------------------------------------------------------------------------
__device__ __forceinline__ unsigned long long ffma2(
    unsigned long long a, unsigned long long b, unsigned long long c)
{
    unsigned long long d;
    asm("fma.rn.f32x2 %0, %1, %2, %3;" : "=l"(d) : "l"(a), "l"(b), "l"(c));
    return d;
}

__global__ __launch_bounds__(512, 2) void main_kernel(
    const float* __restrict__ x, const float* __restrict__ W,
    const float* __restrict__ bias, float* __restrict__ out)
{
    extern __shared__ float smem[];
    float* xs  = smem;              // 4 rows x 2048 floats (32 KB)
    float* red = smem;              // aliased after loop: 128 x 65 floats

    __shared__ int   s_bidx[4];
    __shared__ float s_gvl[4];
    __shared__ int   s_meta[4];     // {active, c0, s0, cnt}

    const int bid = blockIdx.x;
    const int tid = threadIdx.x;

    // ---- warp 0: rebuild worklist from g_gates, locate this CTA's item ----
    if (tid < 32) {
        const int lane = tid;
        if (lane < 4) { s_bidx[lane] = 0; s_gvl[lane] = 0.f; }
        __syncwarp();

        // lane = batch: load its 16 gates
        const float4* gr = (const float4*)(g_gates + lane * NBLK);
        const float4 a0 = gr[0], a1 = gr[1], a2 = gr[2], a3 = gr[3];
        float v[NBLK] = {a0.x,a0.y,a0.z,a0.w, a1.x,a1.y,a1.z,a1.w,
                         a2.x,a2.y,a2.z,a2.w, a3.x,a3.y,a3.z,a3.w};
        unsigned mask16 = 0;
#pragma unroll
        for (int j = 0; j < NBLK; j++)
            if (v[j] != 0.f) mask16 |= 1u << j;

        const int my_item = bid >> 2;
        int total = 0, sel_nb = -1, sel_chunk = 0;
#pragma unroll
        for (int j = 0; j < NBLK; j++) {
            const unsigned m = __ballot_sync(0xffffffffu, (mask16 >> j) & 1u);
            const int ch = (__popc(m) + 3) >> 2;       // chunks of 4 slots
            if (my_item >= total && my_item < total + ch) {
                sel_nb = j; sel_chunk = my_item - total;
            }
            total += ch;
        }

        if (sel_nb >= 0) {
            const unsigned m = __ballot_sync(0xffffffffu, (mask16 >> sel_nb) & 1u);
            const int cnt  = __popc(m);
            const int s0   = sel_chunk * 4;
            const bool act = (mask16 >> sel_nb) & 1u;
            const int r    = __popc(m & ((1u << lane) - 1u));
            if (act && r >= s0 && r < s0 + 4) {
                s_bidx[r - s0] = lane;
                s_gvl[r - s0]  = v[sel_nb];
            }
            if (lane == 0) {
                s_meta[0] = 1;
                s_meta[1] = sel_nb * 128 + (bid & 3) * 32;   // c0
                s_meta[2] = s0;
                s_meta[3] = cnt;
            }
        } else if (lane == 0) {
            s_meta[0] = 0;
        }
    }
    __syncthreads();

    if (!s_meta[0]) return;              // contiguous tail -> fast exit
    const int c0  = s_meta[1];
    const int s0  = s_meta[2];
    const int cnt = s_meta[3];

    // stage x rows (coalesced float4): 4 rows x 512 float4
    for (int m = tid; m < 2048; m += 512) {
        const int s  = m >> 9;
        const int k4 = m & 511;
        ((float4*)(xs + s * DD))[k4] =
            ((const float4*)(x + (size_t)s_bidx[s] * DD))[k4];
    }
    __syncthreads();

    const int kg = tid & 63;             // 0..63 k-quad groups (lanes contiguous)
    const int cg = tid >> 6;             // 0..7 col-groups x 4 rows = 32 rows

    // W rows for this thread's 4 output columns, as k-quad (16 B) stream
    const ulonglong2* w128 = (const ulonglong2*)(W + (size_t)(c0 + cg * 4) * DD);

    unsigned long long acc[4][4];
#pragma unroll
    for (int s = 0; s < 4; s++)
#pragma unroll
        for (int c = 0; c < 4; c++) acc[s][c] = 0ull;

#pragma unroll
    for (int i = 0; i < 8; i++) {        // 8 superiters x 4 k-values
        const int q = kg + i * 64;       // k-quad index (k = 4q..4q+3)

        ulonglong2 wv[4];                // 4x LDG.128
#pragma unroll
        for (int c = 0; c < 4; c++) wv[c] = w128[c * 512 + q];

        ulonglong2 xv[4];                // 4x LDS.128
#pragma unroll
        for (int s = 0; s < 4; s++)
            xv[s] = *(const ulonglong2*)(xs + s * DD + (q << 2));

#pragma unroll
        for (int c = 0; c < 4; c++) {
#pragma unroll
            for (int s = 0; s < 4; s++) {
                acc[s][c] = ffma2(xv[s].x, wv[c].x, acc[s][c]);
                acc[s][c] = ffma2(xv[s].y, wv[c].y, acc[s][c]);
            }
        }
    }
    __syncthreads();                     // xs dead; alias as reduction buffer

    // horizontal add, conflict-free partial store:
    // red[(s*32 + cg*4 + c)*65 + kg] -> bank (idx + kg) % 32, all distinct
#pragma unroll
    for (int s = 0; s < 4; s++) {
#pragma unroll
        for (int c = 0; c < 4; c++) {
            const unsigned long long v = acc[s][c];
            const float lo = __uint_as_float((unsigned)(v & 0xffffffffu));
            const float hi = __uint_as_float((unsigned)(v >> 32));
            red[(s * 32 + cg * 4 + c) * 65 + kg] = lo + hi;
        }
    }
    __syncthreads();

    if (tid < 128) {
        const int s  = tid >> 5;         // local slot 0..3
        const int cp = tid & 31;         // local col 0..31
        const float* r = red + tid * 65;
        float a0 = 0.f, a1 = 0.f, a2 = 0.f, a3 = 0.f;
#pragma unroll
        for (int k = 0; k < 64; k += 4) {
            a0 += r[k]; a1 += r[k + 1]; a2 += r[k + 2]; a3 += r[k + 3];
        }
        const float sum = (a0 + a1) + (a2 + a3);
        if (s0 + s < cnt)
            out[(size_t)s_bidx[s] * DD + c0 + cp] = s_gvl[s] * sum + bias[c0 + cp];
    }
}

// ---------------------------------------------------------------------------
extern "C" void kernel_launch(void* const* d_in, const int* in_sizes, int n_in,
                              void* d_out, int out_size)
{
    (void)in_sizes; (void)n_in; (void)out_size;
    const float* x    = (const float*)d_in[0];
    const float* gw   = (const float*)d_in[1];
    const float* gb   = (const float*)d_in[2];
    const float* W    = (const float*)d_in[3];
    const float* bias = (const float*)d_in[4];
    float* out = (float*)d_out;

    static int smem_set = 0;
    if (!smem_set) {
        cudaFuncSetAttribute(main_kernel,
                             cudaFuncAttributeMaxDynamicSharedMemorySize,
                             128 * 65 * 4);   // 33280 B (xs 32 KB aliased inside)
        smem_set = 1;
    }

    gate_kernel<<<32, 512>>>(x, gw, gb, bias, out);
    // max items = sum ceil(cnt/4) <= (256 + 16*3)/4 = 76 -> grid = 4*76 = 304
    main_kernel<<<304, 512, 128 * 65 * 4>>>(x, W, bias, out);
}